// round 1
// baseline (speedup 1.0000x reference)
#include <cuda_runtime.h>
#include <cstddef>
#include <cstdint>
#include <math.h>

#define BB 32
#define CC 128
#define NN 2025
#define TK 9
#define NG 4
#define CPG 32
#define ROWS_TOT (BB*NN)   // 64800

// ---------------- scratch (device globals; no allocation allowed) ----------------
__device__ float g_xn[(size_t)BB*NN*CC];   // normalized features [B][N][C]
__device__ float g_xt[(size_t)BB*NN*CC];   // GEMM out / of scratch
__device__ float g_h [(size_t)BB*NN*CC];   // gather out / GN input
__device__ float g_vw[(size_t)BB*NN*TK];   // normalized top-k weights
__device__ int   g_ix[(size_t)BB*NN*TK];   // top-k indices
__device__ float g_st[BB*NG*2];            // (mean, rstd) per (b, group)

// ---------------- packed f32x2 helpers ----------------
__device__ __forceinline__ unsigned long long pk2(float lo, float hi){
    unsigned long long r;
    asm("mov.b64 %0,{%1,%2};" : "=l"(r) : "f"(lo), "f"(hi));
    return r;
}
__device__ __forceinline__ unsigned long long f2fma(unsigned long long a,
                                                    unsigned long long b,
                                                    unsigned long long c){
    unsigned long long r;
    asm("fma.rn.f32x2 %0,%1,%2,%3;" : "=l"(r) : "l"(a), "l"(b), "l"(c));
    return r;
}
__device__ __forceinline__ float lo2(unsigned long long v){
    return __uint_as_float((unsigned)(v & 0xffffffffull));
}
__device__ __forceinline__ float hi2(unsigned long long v){
    return __uint_as_float((unsigned)(v >> 32));
}

// ---------------- K1: L2-normalize, transpose [B,C,N] -> [B,N,C] ----------------
__global__ void knorm(const float* __restrict__ x){
    __shared__ float s[CC][33];
    __shared__ float rn[32];
    const int b  = blockIdx.y;
    const int n0 = blockIdx.x * 32;
    const int tid = threadIdx.x;          // 256

    #pragma unroll
    for(int it=0; it<16; ++it){
        int idx = it*256 + tid;
        int c = idx >> 5, nl = idx & 31;
        int n = n0 + nl;
        s[c][nl] = (n < NN) ? x[((size_t)b*CC + c)*NN + n] : 0.f;
    }
    __syncthreads();
    {
        int t = tid & 7, nl = tid >> 3;   // 8 threads per n
        float ss = 0.f;
        #pragma unroll
        for(int c=t; c<CC; c+=8){ float v = s[c][nl]; ss += v*v; }
        ss += __shfl_down_sync(0xffffffffu, ss, 4);
        ss += __shfl_down_sync(0xffffffffu, ss, 2);
        ss += __shfl_down_sync(0xffffffffu, ss, 1);
        if(t == 0){
            float nrm = sqrtf(ss);
            rn[nl] = 1.f / fmaxf(nrm, 1e-12f);
        }
    }
    __syncthreads();
    #pragma unroll
    for(int it=0; it<16; ++it){
        int idx = it*256 + tid;
        int nl = idx >> 7, c = idx & 127;
        int n = n0 + nl;
        if(n < NN) g_xn[((size_t)b*NN + n)*CC + c] = s[c][nl] * rn[nl];
    }
}

// ---------------- K2: fused cosine-sim GEMM + top-9 + weight normalize ----------
// block: 256 thr, tile 64 queries x 128 keys, K=128. f32x2 FMA, warp-broadcast A.
__global__ void __launch_bounds__(256,1) ksimtopk(){
    extern __shared__ float sm[];
    float* As = sm;                    // [128][68]  A^T (c-major)
    float* Bs = As + 128*68;           // [128][132] B^T (c-major)
    float* Ss = Bs + 128*132;          // [64][132]  sim tile
    float* tv = Ss + 64*132;           // [9][64]    running top-9 values
    int*   ti = (int*)(tv + 9*64);     // [9][64]    running top-9 indices

    const int tid  = threadIdx.x;
    const int lane = tid & 31, wq = tid >> 5;   // warp owns 8 queries, lane owns 4 keys
    const int b = blockIdx.y, q0 = blockIdx.x * 64;
    const float* xb = g_xn + (size_t)b*NN*CC;

    #pragma unroll
    for(int it=0; it<32; ++it){
        int idx = it*256 + tid;
        int ql = idx >> 7, c = idx & 127;
        int q = q0 + ql;
        As[c*68 + ql] = (q < NN) ? xb[(size_t)q*CC + c] : 0.f;
    }
    if(tid < 64){
        #pragma unroll
        for(int j=0; j<TK; ++j){ tv[j*64 + tid] = -1e30f; ti[j*64 + tid] = 0; }
    }
    float minv = -1e30f; int minp = 0;
    __syncthreads();

    for(int m0 = 0; m0 < NN; m0 += 128){
        // stage key tile
        #pragma unroll
        for(int it=0; it<64; ++it){
            int idx = it*256 + tid;
            int ml = idx >> 7, c = idx & 127;
            int m = m0 + ml;
            Bs[c*132 + ml] = (m < NN) ? xb[(size_t)m*CC + c] : 0.f;
        }
        __syncthreads();

        unsigned long long acc[4][4];   // [k 0..3][q-pair 0..3]
        #pragma unroll
        for(int k=0;k<4;++k)
            #pragma unroll
            for(int p=0;p<4;++p) acc[k][p] = 0ull;

        #pragma unroll 4
        for(int c=0; c<CC; ++c){
            ulonglong2 aA = *(const ulonglong2*)&As[c*68 + 8*wq];      // broadcast
            ulonglong2 aB = *(const ulonglong2*)&As[c*68 + 8*wq + 4];  // broadcast
            float4 bf = *(const float4*)&Bs[c*132 + 4*lane];
            unsigned long long bd0 = pk2(bf.x, bf.x);
            unsigned long long bd1 = pk2(bf.y, bf.y);
            unsigned long long bd2 = pk2(bf.z, bf.z);
            unsigned long long bd3 = pk2(bf.w, bf.w);
            acc[0][0]=f2fma(aA.x,bd0,acc[0][0]); acc[0][1]=f2fma(aA.y,bd0,acc[0][1]);
            acc[0][2]=f2fma(aB.x,bd0,acc[0][2]); acc[0][3]=f2fma(aB.y,bd0,acc[0][3]);
            acc[1][0]=f2fma(aA.x,bd1,acc[1][0]); acc[1][1]=f2fma(aA.y,bd1,acc[1][1]);
            acc[1][2]=f2fma(aB.x,bd1,acc[1][2]); acc[1][3]=f2fma(aB.y,bd1,acc[1][3]);
            acc[2][0]=f2fma(aA.x,bd2,acc[2][0]); acc[2][1]=f2fma(aA.y,bd2,acc[2][1]);
            acc[2][2]=f2fma(aB.x,bd2,acc[2][2]); acc[2][3]=f2fma(aB.y,bd2,acc[2][3]);
            acc[3][0]=f2fma(aA.x,bd3,acc[3][0]); acc[3][1]=f2fma(aA.y,bd3,acc[3][1]);
            acc[3][2]=f2fma(aB.x,bd3,acc[3][2]); acc[3][3]=f2fma(aB.y,bd3,acc[3][3]);
        }

        // spill sim tile to smem: acc[k][p] = {sim[2p][k], sim[2p+1][k]}
        #pragma unroll
        for(int p=0; p<4; ++p){
            int q = 8*wq + 2*p;
            float4 v0 = make_float4(lo2(acc[0][p]), lo2(acc[1][p]),
                                    lo2(acc[2][p]), lo2(acc[3][p]));
            float4 v1 = make_float4(hi2(acc[0][p]), hi2(acc[1][p]),
                                    hi2(acc[2][p]), hi2(acc[3][p]));
            *(float4*)&Ss[(size_t)q*132 + 4*lane]     = v0;
            *(float4*)&Ss[(size_t)(q+1)*132 + 4*lane] = v1;
        }
        __syncthreads();

        // per-query top-9 merge (thread tid owns query row tid)
        if(tid < 64){
            int lim = NN - m0; if(lim > 128) lim = 128;
            const float* srow = Ss + (size_t)tid*132;
            for(int j=0; j<lim; ++j){
                float v = srow[j];
                if(v > minv){
                    tv[minp*64 + tid] = v;
                    ti[minp*64 + tid] = m0 + j;
                    float mv = tv[tid]; int mp = 0;
                    #pragma unroll
                    for(int u=1; u<TK; ++u){
                        float t2 = tv[u*64 + tid];
                        if(t2 < mv){ mv = t2; mp = u; }
                    }
                    minv = mv; minp = mp;
                }
            }
        }
        __syncthreads();
    }

    int q = q0 + tid;
    if(tid < 64 && q < NN){
        float s = 0.f;
        #pragma unroll
        for(int j=0; j<TK; ++j) s += tv[j*64 + tid];
        float inv = 1.f / (s + 1e-6f);
        size_t base = ((size_t)b*NN + q)*TK;
        #pragma unroll
        for(int j=0; j<TK; ++j){
            g_vw[base + j] = tv[j*64 + tid] * inv;
            g_ix[base + j] = ti[j*64 + tid];
        }
    }
}

// ---------------- K3: out[r][:] = A[r][:] @ W  (rows x 128 @ 128 x 128) --------
__global__ void __launch_bounds__(256,2) kgemm(const float* __restrict__ A,
                                              const float* __restrict__ W,
                                              float* __restrict__ out, int rows){
    extern __shared__ float sm[];
    float* As = sm;            // [128][68]  A^T
    float* Ws = As + 128*68;   // [128][128] W row-major
    const int tid = threadIdx.x, lane = tid & 31, wq = tid >> 5;
    const int r0 = blockIdx.x * 64;

    #pragma unroll
    for(int it=0; it<32; ++it){
        int idx = it*256 + tid;
        int rl = idx >> 7, c = idx & 127;
        int r = r0 + rl;
        As[c*68 + rl] = (r < rows) ? A[(size_t)r*CC + c] : 0.f;
    }
    #pragma unroll
    for(int it=0; it<64; ++it){ int idx = it*256 + tid; Ws[idx] = W[idx]; }
    __syncthreads();

    unsigned long long acc[4][4];
    #pragma unroll
    for(int k=0;k<4;++k)
        #pragma unroll
        for(int p=0;p<4;++p) acc[k][p] = 0ull;

    #pragma unroll 4
    for(int c=0; c<CC; ++c){
        ulonglong2 aA = *(const ulonglong2*)&As[c*68 + 8*wq];
        ulonglong2 aB = *(const ulonglong2*)&As[c*68 + 8*wq + 4];
        float4 bf = *(const float4*)&Ws[c*CC + 4*lane];
        unsigned long long bd0 = pk2(bf.x, bf.x);
        unsigned long long bd1 = pk2(bf.y, bf.y);
        unsigned long long bd2 = pk2(bf.z, bf.z);
        unsigned long long bd3 = pk2(bf.w, bf.w);
        acc[0][0]=f2fma(aA.x,bd0,acc[0][0]); acc[0][1]=f2fma(aA.y,bd0,acc[0][1]);
        acc[0][2]=f2fma(aB.x,bd0,acc[0][2]); acc[0][3]=f2fma(aB.y,bd0,acc[0][3]);
        acc[1][0]=f2fma(aA.x,bd1,acc[1][0]); acc[1][1]=f2fma(aA.y,bd1,acc[1][1]);
        acc[1][2]=f2fma(aB.x,bd1,acc[1][2]); acc[1][3]=f2fma(aB.y,bd1,acc[1][3]);
        acc[2][0]=f2fma(aA.x,bd2,acc[2][0]); acc[2][1]=f2fma(aA.y,bd2,acc[2][1]);
        acc[2][2]=f2fma(aB.x,bd2,acc[2][2]); acc[2][3]=f2fma(aB.y,bd2,acc[2][3]);
        acc[3][0]=f2fma(aA.x,bd3,acc[3][0]); acc[3][1]=f2fma(aA.y,bd3,acc[3][1]);
        acc[3][2]=f2fma(aB.x,bd3,acc[3][2]); acc[3][3]=f2fma(aB.y,bd3,acc[3][3]);
    }

    #pragma unroll
    for(int p=0; p<4; ++p){
        int r = r0 + 8*wq + 2*p;
        float4 v0 = make_float4(lo2(acc[0][p]), lo2(acc[1][p]),
                                lo2(acc[2][p]), lo2(acc[3][p]));
        float4 v1 = make_float4(hi2(acc[0][p]), hi2(acc[1][p]),
                                hi2(acc[2][p]), hi2(acc[3][p]));
        if(r     < rows) *(float4*)&out[(size_t)r*CC + 4*lane]     = v0;
        if(r + 1 < rows) *(float4*)&out[(size_t)(r+1)*CC + 4*lane] = v1;
    }
}

// ---------------- K4: KNN gather + weighted sum + bias -------------------------
__global__ void kgather(const float* __restrict__ xt, const float* __restrict__ bias,
                        float* __restrict__ h){
    const int bn = blockIdx.x;            // 0..64799
    const int b  = bn / NN;
    __shared__ float vs[TK];
    __shared__ int   is[TK];
    const int tid = threadIdx.x;          // 128
    if(tid < TK){
        vs[tid] = g_vw[(size_t)bn*TK + tid];
        is[tid] = g_ix[(size_t)bn*TK + tid];
    }
    __syncthreads();
    const float* xb = xt + (size_t)b*NN*CC;
    float a = bias[tid];
    #pragma unroll
    for(int k=0; k<TK; ++k) a += vs[k] * xb[(size_t)is[k]*CC + tid];
    h[(size_t)bn*CC + tid] = a;
}

// ---------------- K5: GroupNorm stats (mean, rstd) per (b, group) --------------
__global__ void kgnstat(const float* __restrict__ h){
    const int bg = blockIdx.x;            // 0..127
    const int b = bg >> 2, g = bg & 3;
    const int tid = threadIdx.x;          // 256
    const float* hb = h + (size_t)b*NN*CC + g*CPG;
    float s = 0.f, s2 = 0.f;
    for(int i = tid; i < NN*CPG; i += 256){
        int n = i >> 5, cc = i & 31;
        float v = hb[(size_t)n*CC + cc];
        s += v; s2 += v*v;
    }
    __shared__ float rs[8], rs2[8];
    #pragma unroll
    for(int o=16; o; o>>=1){
        s  += __shfl_down_sync(0xffffffffu, s,  o);
        s2 += __shfl_down_sync(0xffffffffu, s2, o);
    }
    if((tid & 31) == 0){ rs[tid>>5] = s; rs2[tid>>5] = s2; }
    __syncthreads();
    if(tid < 8){
        s = rs[tid]; s2 = rs2[tid];
        #pragma unroll
        for(int o=4; o; o>>=1){
            s  += __shfl_down_sync(0xffu, s,  o);
            s2 += __shfl_down_sync(0xffu, s2, o);
        }
        if(tid == 0){
            const float cnt = (float)(NN*CPG);
            float mean = s / cnt;
            float var  = s2 / cnt - mean*mean;
            g_st[bg*2]     = mean;
            g_st[bg*2 + 1] = rsqrtf(var + 1e-5f);
        }
    }
}

// ---------------- K6: GN apply + SiLU (optional transpose to [B,C,N]) ----------
__global__ void kgnapply(const float* __restrict__ h, const float* __restrict__ gamma,
                         const float* __restrict__ beta, float* __restrict__ out,
                         int transpose){
    const size_t e = (size_t)blockIdx.x*256 + threadIdx.x;
    if(e >= (size_t)BB*NN*CC) return;
    const int c  = (int)(e & 127);
    const int bn = (int)(e >> 7);
    const int b = bn / NN, n = bn % NN;
    const int g = c >> 5;
    const float mean = g_st[(b*NG + g)*2];
    const float rstd = g_st[(b*NG + g)*2 + 1];
    float y = (h[e] - mean) * rstd * gamma[c] + beta[c];
    float sv = y / (1.f + expf(-y));
    if(transpose) out[((size_t)b*CC + c)*NN + n] = sv;
    else          out[e] = sv;
}

// ---------------- launch ----------------
extern "C" void kernel_launch(void* const* d_in, const int* in_sizes, int n_in,
                              void* d_out, int out_size){
    const float* x   = (const float*)d_in[0];
    const float* w1  = (const float*)d_in[1];
    const float* b1  = (const float*)d_in[2];
    const float* w2  = (const float*)d_in[3];
    const float* b2  = (const float*)d_in[4];
    const float* gm1 = (const float*)d_in[5];
    const float* bt1 = (const float*)d_in[6];
    const float* gm2 = (const float*)d_in[7];
    const float* bt2 = (const float*)d_in[8];
    float* out = (float*)d_out;

    const int SM_SIM  = (128*68 + 128*132 + 64*132 + TK*64)*4 + TK*64*4; // 140800
    const int SM_GEMM = (128*68 + 128*128)*4;                            // 100352
    cudaFuncSetAttribute(ksimtopk, cudaFuncAttributeMaxDynamicSharedMemorySize, SM_SIM);
    cudaFuncSetAttribute(kgemm,    cudaFuncAttributeMaxDynamicSharedMemorySize, SM_GEMM);

    float *xn, *xt, *h;
    cudaGetSymbolAddress((void**)&xn, g_xn);
    cudaGetSymbolAddress((void**)&xt, g_xt);
    cudaGetSymbolAddress((void**)&h,  g_h);

    const int gemm_blocks = (ROWS_TOT + 63) / 64;   // 1013

    knorm<<<dim3(64, BB), 256>>>(x);
    ksimtopk<<<dim3(32, BB), 256, SM_SIM>>>();

    // layer 1
    kgemm<<<gemm_blocks, 256, SM_GEMM>>>(xn, w1, xt, ROWS_TOT);
    kgather<<<ROWS_TOT, 128>>>(xt, b1, h);
    kgnstat<<<BB*NG, 256>>>(h);
    kgnapply<<<32400, 256>>>(h, gm1, bt1, xt, 0);    // of -> g_xt

    // layer 2 (g_xn is free now; reuse for xt2)
    kgemm<<<gemm_blocks, 256, SM_GEMM>>>(xt, w2, xn, ROWS_TOT);
    kgather<<<ROWS_TOT, 128>>>(xn, b2, h);
    kgnstat<<<BB*NG, 256>>>(h);
    kgnapply<<<32400, 256>>>(h, gm2, bt2, out, 1);   // final, [B,C,H,W]
}

// round 2
// speedup vs baseline: 1.0078x; 1.0078x over previous
#include <cuda_runtime.h>
#include <cstddef>
#include <cstdint>
#include <math.h>

#define BB 32
#define CC 128
#define NN 2025
#define NPAD 2048
#define TK 9
#define NG 4
#define CPG 32
#define ROWS_TOT (BB*NN)   // 64800

// ---------------- scratch (device globals; no allocation allowed) ----------------
__device__ float g_xn [(size_t)BB*NN*CC];    // normalized features [B][N][C]
__device__ float g_xnT[(size_t)BB*CC*NPAD];  // normalized features [B][C][Npad], zero-padded
__device__ float g_xt [(size_t)BB*NN*CC];    // GEMM out / of scratch
__device__ float g_h  [(size_t)BB*NN*CC];    // gather out / GN input
__device__ float g_vw [(size_t)BB*NN*TK];    // normalized top-k weights
__device__ int   g_ix [(size_t)BB*NN*TK];    // top-k indices
__device__ float g_st [BB*NG*2];             // (mean, rstd) per (b, group)

// ---------------- packed f32x2 helpers ----------------
__device__ __forceinline__ unsigned long long pk2(float lo, float hi){
    unsigned long long r;
    asm("mov.b64 %0,{%1,%2};" : "=l"(r) : "f"(lo), "f"(hi));
    return r;
}
__device__ __forceinline__ unsigned long long f2fma(unsigned long long a,
                                                    unsigned long long b,
                                                    unsigned long long c){
    unsigned long long r;
    asm("fma.rn.f32x2 %0,%1,%2,%3;" : "=l"(r) : "l"(a), "l"(b), "l"(c));
    return r;
}
__device__ __forceinline__ float lo2(unsigned long long v){
    return __uint_as_float((unsigned)(v & 0xffffffffull));
}
__device__ __forceinline__ float hi2(unsigned long long v){
    return __uint_as_float((unsigned)(v >> 32));
}

// ---------------- K1: L2-normalize; write [B,N,C] and padded [B,C,Npad] --------
__global__ void knorm(const float* __restrict__ x){
    __shared__ float s[CC][33];
    __shared__ float rn[32];
    const int b  = blockIdx.y;
    const int n0 = blockIdx.x * 32;
    const int tid = threadIdx.x;          // 256

    #pragma unroll
    for(int it=0; it<16; ++it){
        int idx = it*256 + tid;
        int c = idx >> 5, nl = idx & 31;
        int n = n0 + nl;
        s[c][nl] = (n < NN) ? x[((size_t)b*CC + c)*NN + n] : 0.f;
    }
    __syncthreads();
    {
        int t = tid & 7, nl = tid >> 3;   // 8 threads per n
        float ss = 0.f;
        #pragma unroll
        for(int c=t; c<CC; c+=8){ float v = s[c][nl]; ss += v*v; }
        ss += __shfl_down_sync(0xffffffffu, ss, 4);
        ss += __shfl_down_sync(0xffffffffu, ss, 2);
        ss += __shfl_down_sync(0xffffffffu, ss, 1);
        if(t == 0){
            float nrm = sqrtf(ss);
            rn[nl] = 1.f / fmaxf(nrm, 1e-12f);
        }
    }
    __syncthreads();
    // row-major [B,N,C]
    #pragma unroll
    for(int it=0; it<16; ++it){
        int idx = it*256 + tid;
        int nl = idx >> 7, c = idx & 127;
        int n = n0 + nl;
        if(n < NN) g_xn[((size_t)b*NN + n)*CC + c] = s[c][nl] * rn[nl];
    }
    // transposed padded [B,C,Npad] (n >= NN lanes write exact zeros)
    #pragma unroll
    for(int it=0; it<16; ++it){
        int idx = it*256 + tid;
        int c = idx >> 5, nl = idx & 31;
        int n = n0 + nl;
        g_xnT[((size_t)b*CC + c)*NPAD + n] = s[c][nl] * rn[nl];
    }
}

// ---------------- K2: fused cosine-sim GEMM + top-9 + weight normalize ----------
// 256 thr, tile 64q x 128k, K=128. f32x2 FMA; reg-prefetch double buffer;
// ballot-driven top-9 merge from accumulators (no sim spill).
__global__ void __launch_bounds__(256,1) ksimtopk(){
    extern __shared__ float sm[];
    float* As = sm;                    // [128][64]  A^T (c-major)
    float* Bs = As + 128*64;           // [2][128][128] B^T double buffer
    float* tv = Bs + 2*128*128;        // [9][64] running top-9 values
    int*   ti = (int*)(tv + TK*64);    // [9][64] running top-9 indices

    const int tid  = threadIdx.x;
    const int lane = tid & 31, wq = tid >> 5;   // warp: 8 queries; lane: 4 keys
    const int b = blockIdx.y, q0 = blockIdx.x * 64;
    const float* xT = g_xnT + (size_t)b*CC*NPAD;

    // stage A tile [128c][64q] — coalesced float4 LDG, conflict-free STS.128
    #pragma unroll
    for(int r=0; r<8; ++r){
        int c  = r*16 + (tid >> 4);
        int qq = (tid & 15) * 4;
        float4 v = *(const float4*)&xT[(size_t)c*NPAD + q0 + qq];
        *(float4*)&As[c*64 + qq] = v;
    }
    // stage key tile 0 into buf 0
    #pragma unroll
    for(int r=0; r<16; ++r){
        int c = r*8 + wq;
        float4 v = *(const float4*)&xT[(size_t)c*NPAD + 4*lane];
        *(float4*)&Bs[c*128 + 4*lane] = v;
    }
    if(tid < 64){
        #pragma unroll
        for(int j=0; j<TK; ++j){ tv[j*64 + tid] = -1e30f; ti[j*64 + tid] = 0; }
    }
    float mn[8]; int mp[8];
    #pragma unroll
    for(int j=0; j<8; ++j){ mn[j] = -1e30f; mp[j] = 0; }
    __syncthreads();

    const int NT = NPAD / 128;  // 16 tiles
    for(int t = 0; t < NT; ++t){
        const int cur = t & 1;
        const int m0  = t * 128;

        // prefetch next key tile into registers (MLP=16)
        float4 pf[16];
        if(t + 1 < NT){
            const int m0n = m0 + 128;
            #pragma unroll
            for(int r=0; r<16; ++r){
                int c = r*8 + wq;
                pf[r] = *(const float4*)&xT[(size_t)c*NPAD + m0n + 4*lane];
            }
        }

        // ---- compute 64x128 sim tile ----
        const float* Bc = Bs + cur*(128*128);
        unsigned long long acc[4][4];
        #pragma unroll
        for(int k=0;k<4;++k)
            #pragma unroll
            for(int p=0;p<4;++p) acc[k][p] = 0ull;

        #pragma unroll 4
        for(int c=0; c<CC; ++c){
            ulonglong2 aA = *(const ulonglong2*)&As[c*64 + 8*wq];      // broadcast
            ulonglong2 aB = *(const ulonglong2*)&As[c*64 + 8*wq + 4];  // broadcast
            float4 bf = *(const float4*)&Bc[c*128 + 4*lane];
            unsigned long long bd0 = pk2(bf.x, bf.x);
            unsigned long long bd1 = pk2(bf.y, bf.y);
            unsigned long long bd2 = pk2(bf.z, bf.z);
            unsigned long long bd3 = pk2(bf.w, bf.w);
            acc[0][0]=f2fma(aA.x,bd0,acc[0][0]); acc[0][1]=f2fma(aA.y,bd0,acc[0][1]);
            acc[0][2]=f2fma(aB.x,bd0,acc[0][2]); acc[0][3]=f2fma(aB.y,bd0,acc[0][3]);
            acc[1][0]=f2fma(aA.x,bd1,acc[1][0]); acc[1][1]=f2fma(aA.y,bd1,acc[1][1]);
            acc[1][2]=f2fma(aB.x,bd1,acc[1][2]); acc[1][3]=f2fma(aB.y,bd1,acc[1][3]);
            acc[2][0]=f2fma(aA.x,bd2,acc[2][0]); acc[2][1]=f2fma(aA.y,bd2,acc[2][1]);
            acc[2][2]=f2fma(aB.x,bd2,acc[2][2]); acc[2][3]=f2fma(aB.y,bd2,acc[2][3]);
            acc[3][0]=f2fma(aA.x,bd3,acc[3][0]); acc[3][1]=f2fma(aA.y,bd3,acc[3][1]);
            acc[3][2]=f2fma(aB.x,bd3,acc[3][2]); acc[3][3]=f2fma(aB.y,bd3,acc[3][3]);
        }

        // store prefetched tile into the other buffer
        if(t + 1 < NT){
            float* Bn = Bs + (1-cur)*(128*128);
            #pragma unroll
            for(int r=0; r<16; ++r){
                int c = r*8 + wq;
                *(float4*)&Bn[c*128 + 4*lane] = pf[r];
            }
        }

        // ---- ballot-driven top-9 merge (each warp: its own 8 queries) ----
        // key validity (only last tile has padded keys)
        bool kv0 = (m0 + 4*lane + 0) < NN;
        bool kv1 = (m0 + 4*lane + 1) < NN;
        bool kv2 = (m0 + 4*lane + 2) < NN;
        bool kv3 = (m0 + 4*lane + 3) < NN;

        #pragma unroll
        for(int j=0; j<8; ++j){
            const int p = j >> 1, h = j & 1;
            const int q = 8*wq + j;
            float v0 = h ? hi2(acc[0][p]) : lo2(acc[0][p]); if(!kv0) v0 = -1e30f;
            float v1 = h ? hi2(acc[1][p]) : lo2(acc[1][p]); if(!kv1) v1 = -1e30f;
            float v2 = h ? hi2(acc[2][p]) : lo2(acc[2][p]); if(!kv2) v2 = -1e30f;
            float v3 = h ? hi2(acc[3][p]) : lo2(acc[3][p]); if(!kv3) v3 = -1e30f;
            float mnv = mn[j];
            unsigned bal = __ballot_sync(0xffffffffu,
                (v0 > mnv) | (v1 > mnv) | (v2 > mnv) | (v3 > mnv));
            while(bal){
                // each lane picks its local best
                float bv = v0; int bk = 0;
                if(v1 > bv){ bv = v1; bk = 1; }
                if(v2 > bv){ bv = v2; bk = 2; }
                if(v3 > bv){ bv = v3; bk = 3; }
                int src = __ffs(bal) - 1;
                float cand = __shfl_sync(0xffffffffu, bv, src);
                int   ck   = __shfl_sync(0xffffffffu, bk, src);
                int   cm   = m0 + 4*src + ck;
                // consume on src lane
                if(lane == src){
                    if(bk == 0) v0 = -1e30f;
                    else if(bk == 1) v1 = -1e30f;
                    else if(bk == 2) v2 = -1e30f;
                    else v3 = -1e30f;
                }
                if(cand > mnv){
                    if(lane == 0){
                        tv[mp[j]*64 + q] = cand;
                        ti[mp[j]*64 + q] = cm;
                    }
                    __syncwarp();
                    // parallel 9-way min reduce
                    float tmin = (lane < TK) ? tv[lane*64 + q] : 3e38f;
                    int   smin = lane;
                    #pragma unroll
                    for(int off=16; off; off>>=1){
                        float ot = __shfl_down_sync(0xffffffffu, tmin, off);
                        int   os = __shfl_down_sync(0xffffffffu, smin, off);
                        if(ot < tmin){ tmin = ot; smin = os; }
                    }
                    mnv   = __shfl_sync(0xffffffffu, tmin, 0);
                    mp[j] = __shfl_sync(0xffffffffu, smin, 0);
                }
                bal = __ballot_sync(0xffffffffu,
                    (v0 > mnv) | (v1 > mnv) | (v2 > mnv) | (v3 > mnv));
            }
            mn[j] = mnv;
        }
        __syncthreads();
    }

    // finalize: normalize weights, write out
    int q = q0 + tid;
    if(tid < 64 && q < NN){
        float s = 0.f;
        #pragma unroll
        for(int j=0; j<TK; ++j) s += tv[j*64 + tid];
        float inv = 1.f / (s + 1e-6f);
        size_t base = ((size_t)b*NN + q)*TK;
        #pragma unroll
        for(int j=0; j<TK; ++j){
            g_vw[base + j] = tv[j*64 + tid] * inv;
            g_ix[base + j] = ti[j*64 + tid];
        }
    }
}

// ---------------- K3: out[r][:] = A[r][:] @ W  (rows x 128 @ 128 x 128) --------
__global__ void __launch_bounds__(256,2) kgemm(const float* __restrict__ A,
                                              const float* __restrict__ W,
                                              float* __restrict__ out, int rows){
    extern __shared__ float sm[];
    float* As = sm;            // [128][68]  A^T
    float* Ws = As + 128*68;   // [128][128] W row-major
    const int tid = threadIdx.x, lane = tid & 31, wq = tid >> 5;
    const int r0 = blockIdx.x * 64;

    #pragma unroll
    for(int it=0; it<32; ++it){
        int idx = it*256 + tid;
        int rl = idx >> 7, c = idx & 127;
        int r = r0 + rl;
        As[c*68 + rl] = (r < rows) ? A[(size_t)r*CC + c] : 0.f;
    }
    #pragma unroll
    for(int it=0; it<64; ++it){ int idx = it*256 + tid; Ws[idx] = W[idx]; }
    __syncthreads();

    unsigned long long acc[4][4];
    #pragma unroll
    for(int k=0;k<4;++k)
        #pragma unroll
        for(int p=0;p<4;++p) acc[k][p] = 0ull;

    #pragma unroll 4
    for(int c=0; c<CC; ++c){
        ulonglong2 aA = *(const ulonglong2*)&As[c*68 + 8*wq];
        ulonglong2 aB = *(const ulonglong2*)&As[c*68 + 8*wq + 4];
        float4 bf = *(const float4*)&Ws[c*CC + 4*lane];
        unsigned long long bd0 = pk2(bf.x, bf.x);
        unsigned long long bd1 = pk2(bf.y, bf.y);
        unsigned long long bd2 = pk2(bf.z, bf.z);
        unsigned long long bd3 = pk2(bf.w, bf.w);
        acc[0][0]=f2fma(aA.x,bd0,acc[0][0]); acc[0][1]=f2fma(aA.y,bd0,acc[0][1]);
        acc[0][2]=f2fma(aB.x,bd0,acc[0][2]); acc[0][3]=f2fma(aB.y,bd0,acc[0][3]);
        acc[1][0]=f2fma(aA.x,bd1,acc[1][0]); acc[1][1]=f2fma(aA.y,bd1,acc[1][1]);
        acc[1][2]=f2fma(aB.x,bd1,acc[1][2]); acc[1][3]=f2fma(aB.y,bd1,acc[1][3]);
        acc[2][0]=f2fma(aA.x,bd2,acc[2][0]); acc[2][1]=f2fma(aA.y,bd2,acc[2][1]);
        acc[2][2]=f2fma(aB.x,bd2,acc[2][2]); acc[2][3]=f2fma(aB.y,bd2,acc[2][3]);
        acc[3][0]=f2fma(aA.x,bd3,acc[3][0]); acc[3][1]=f2fma(aA.y,bd3,acc[3][1]);
        acc[3][2]=f2fma(aB.x,bd3,acc[3][2]); acc[3][3]=f2fma(aB.y,bd3,acc[3][3]);
    }

    #pragma unroll
    for(int p=0; p<4; ++p){
        int r = r0 + 8*wq + 2*p;
        float4 v0 = make_float4(lo2(acc[0][p]), lo2(acc[1][p]),
                                lo2(acc[2][p]), lo2(acc[3][p]));
        float4 v1 = make_float4(hi2(acc[0][p]), hi2(acc[1][p]),
                                hi2(acc[2][p]), hi2(acc[3][p]));
        if(r     < rows) *(float4*)&out[(size_t)r*CC + 4*lane]     = v0;
        if(r + 1 < rows) *(float4*)&out[(size_t)(r+1)*CC + 4*lane] = v1;
    }
}

// ---------------- K4: KNN gather + weighted sum + bias -------------------------
__global__ void kgather(const float* __restrict__ xt, const float* __restrict__ bias,
                        float* __restrict__ h){
    const int bn = blockIdx.x;            // 0..64799
    const int b  = bn / NN;
    __shared__ float vs[TK];
    __shared__ int   is[TK];
    const int tid = threadIdx.x;          // 128
    if(tid < TK){
        vs[tid] = g_vw[(size_t)bn*TK + tid];
        is[tid] = g_ix[(size_t)bn*TK + tid];
    }
    __syncthreads();
    const float* xb = xt + (size_t)b*NN*CC;
    float a = bias[tid];
    #pragma unroll
    for(int k=0; k<TK; ++k) a += vs[k] * xb[(size_t)is[k]*CC + tid];
    h[(size_t)bn*CC + tid] = a;
}

// ---------------- K5: GroupNorm stats (mean, rstd) per (b, group) --------------
__global__ void kgnstat(const float* __restrict__ h){
    const int bg = blockIdx.x;            // 0..127
    const int b = bg >> 2, g = bg & 3;
    const int tid = threadIdx.x;          // 256
    const float* hb = h + (size_t)b*NN*CC + g*CPG;
    float s = 0.f, s2 = 0.f;
    for(int i = tid; i < NN*CPG; i += 256){
        int n = i >> 5, cc = i & 31;
        float v = hb[(size_t)n*CC + cc];
        s += v; s2 += v*v;
    }
    __shared__ float rs[8], rs2[8];
    #pragma unroll
    for(int o=16; o; o>>=1){
        s  += __shfl_down_sync(0xffffffffu, s,  o);
        s2 += __shfl_down_sync(0xffffffffu, s2, o);
    }
    if((tid & 31) == 0){ rs[tid>>5] = s; rs2[tid>>5] = s2; }
    __syncthreads();
    if(tid < 8){
        s = rs[tid]; s2 = rs2[tid];
        #pragma unroll
        for(int o=4; o; o>>=1){
            s  += __shfl_down_sync(0xffu, s,  o);
            s2 += __shfl_down_sync(0xffu, s2, o);
        }
        if(tid == 0){
            const float cnt = (float)(NN*CPG);
            float mean = s / cnt;
            float var  = s2 / cnt - mean*mean;
            g_st[bg*2]     = mean;
            g_st[bg*2 + 1] = rsqrtf(var + 1e-5f);
        }
    }
}

// ---------------- K6: GN apply + SiLU (optional transpose to [B,C,N]) ----------
__global__ void kgnapply(const float* __restrict__ h, const float* __restrict__ gamma,
                         const float* __restrict__ beta, float* __restrict__ out,
                         int transpose){
    const size_t e = (size_t)blockIdx.x*256 + threadIdx.x;
    if(e >= (size_t)BB*NN*CC) return;
    const int c  = (int)(e & 127);
    const int bn = (int)(e >> 7);
    const int b = bn / NN, n = bn % NN;
    const int g = c >> 5;
    const float mean = g_st[(b*NG + g)*2];
    const float rstd = g_st[(b*NG + g)*2 + 1];
    float y = (h[e] - mean) * rstd * gamma[c] + beta[c];
    float sv = y / (1.f + expf(-y));
    if(transpose) out[((size_t)b*CC + c)*NN + n] = sv;
    else          out[e] = sv;
}

// ---------------- launch ----------------
extern "C" void kernel_launch(void* const* d_in, const int* in_sizes, int n_in,
                              void* d_out, int out_size){
    const float* x   = (const float*)d_in[0];
    const float* w1  = (const float*)d_in[1];
    const float* b1  = (const float*)d_in[2];
    const float* w2  = (const float*)d_in[3];
    const float* b2  = (const float*)d_in[4];
    const float* gm1 = (const float*)d_in[5];
    const float* bt1 = (const float*)d_in[6];
    const float* gm2 = (const float*)d_in[7];
    const float* bt2 = (const float*)d_in[8];
    float* out = (float*)d_out;

    const int SM_SIM  = (128*64 + 2*128*128 + TK*64)*4 + TK*64*4; // 168448
    const int SM_GEMM = (128*68 + 128*128)*4;                     // 100352
    cudaFuncSetAttribute(ksimtopk, cudaFuncAttributeMaxDynamicSharedMemorySize, SM_SIM);
    cudaFuncSetAttribute(kgemm,    cudaFuncAttributeMaxDynamicSharedMemorySize, SM_GEMM);

    float *xn, *xt, *h;
    cudaGetSymbolAddress((void**)&xn, g_xn);
    cudaGetSymbolAddress((void**)&xt, g_xt);
    cudaGetSymbolAddress((void**)&h,  g_h);

    const int gemm_blocks = (ROWS_TOT + 63) / 64;   // 1013

    knorm<<<dim3(64, BB), 256>>>(x);
    ksimtopk<<<dim3(32, BB), 256, SM_SIM>>>();

    // layer 1
    kgemm<<<gemm_blocks, 256, SM_GEMM>>>(xn, w1, xt, ROWS_TOT);
    kgather<<<ROWS_TOT, 128>>>(xt, b1, h);
    kgnstat<<<BB*NG, 256>>>(h);
    kgnapply<<<32400, 256>>>(h, gm1, bt1, xt, 0);    // of -> g_xt

    // layer 2 (g_xn is free now; reuse for xt2)
    kgemm<<<gemm_blocks, 256, SM_GEMM>>>(xt, w2, xn, ROWS_TOT);
    kgather<<<ROWS_TOT, 128>>>(xn, b2, h);
    kgnstat<<<BB*NG, 256>>>(h);
    kgnapply<<<32400, 256>>>(h, gm2, bt2, out, 1);   // final, [B,C,H,W]
}

// round 5
// speedup vs baseline: 1.9977x; 1.9823x over previous
#include <cuda_runtime.h>
#include <cuda_bf16.h>
#include <cstddef>
#include <cstdint>
#include <math.h>

#define BB 32
#define CC 128
#define NN 2025
#define NPAD 2048
#define TK 9
#define NG 4
#define CPG 32
#define ROWS_TOT (BB*NN)   // 64800

// ---------------- scratch (device globals; no allocation allowed) ----------------
__device__ float g_xn [(size_t)BB*NN*CC];           // normalized features [B][N][C] fp32
__device__ __nv_bfloat16 g_xhi[(size_t)BB*NPAD*CC]; // bf16 hi split, zero-padded rows
__device__ __nv_bfloat16 g_xlo[(size_t)BB*NPAD*CC]; // bf16 lo split, zero-padded rows
__device__ float g_xt [(size_t)BB*NN*CC];           // GEMM out / of scratch
__device__ float g_h  [(size_t)BB*NN*CC];           // gather out / GN input
__device__ float g_vw [(size_t)BB*NN*TK];           // normalized top-k weights
__device__ int   g_ix [(size_t)BB*NN*TK];           // top-k indices
__device__ float g_st [BB*NG*2];                    // (mean, rstd) per (b, group)

// ---------------- packed f32x2 helpers (for kgemm) ----------------
__device__ __forceinline__ unsigned long long pk2(float lo, float hi){
    unsigned long long r;
    asm("mov.b64 %0,{%1,%2};" : "=l"(r) : "f"(lo), "f"(hi));
    return r;
}
__device__ __forceinline__ unsigned long long f2fma(unsigned long long a,
                                                    unsigned long long b,
                                                    unsigned long long c){
    unsigned long long r;
    asm("fma.rn.f32x2 %0,%1,%2,%3;" : "=l"(r) : "l"(a), "l"(b), "l"(c));
    return r;
}
__device__ __forceinline__ float lo2(unsigned long long v){
    return __uint_as_float((unsigned)(v & 0xffffffffull));
}
__device__ __forceinline__ float hi2(unsigned long long v){
    return __uint_as_float((unsigned)(v >> 32));
}

// ---------------- base-ISA async-copy / ldmatrix / mma helpers -----------------
__device__ __forceinline__ uint32_t smem_u32(const void* p){
    uint32_t a;
    asm("{ .reg .u64 t; cvta.to.shared.u64 t, %1; cvt.u32.u64 %0, t; }" : "=r"(a) : "l"(p));
    return a;
}
#define CP_COMMIT() asm volatile("cp.async.commit_group;" ::: "memory")
#define CP_WAIT0()  asm volatile("cp.async.wait_group 0;" ::: "memory")

__device__ __forceinline__ void cp16(uint32_t dst, const void* src){
    asm volatile("cp.async.cg.shared.global [%0], [%1], 16;" :: "r"(dst), "l"(src));
}
__device__ __forceinline__ void ldsm4(uint32_t addr, uint32_t* r){
    asm volatile("ldmatrix.sync.aligned.m8n8.x4.shared.b16 {%0,%1,%2,%3}, [%4];"
        : "=r"(r[0]), "=r"(r[1]), "=r"(r[2]), "=r"(r[3]) : "r"(addr));
}
__device__ __forceinline__ void mma16816(float* d, const uint32_t* a,
                                         uint32_t b0, uint32_t b1){
    asm volatile("mma.sync.aligned.m16n8k16.row.col.f32.bf16.bf16.f32 "
        "{%0,%1,%2,%3}, {%4,%5,%6,%7}, {%8,%9}, {%0,%1,%2,%3};"
        : "+f"(d[0]), "+f"(d[1]), "+f"(d[2]), "+f"(d[3])
        : "r"(a[0]), "r"(a[1]), "r"(a[2]), "r"(a[3]), "r"(b0), "r"(b1));
}

// swizzled tile layout: 128 rows x 128 bf16; row = 256B; chunk(16B) ch stored at
// byte off = row*256 + ((ch ^ (row&7))<<4). conflict-free for ldmatrix + staging.
__device__ __forceinline__ uint32_t afrag_addr(uint32_t base, int rbase, int ks, int lane){
    int row = rbase + (lane & 7) + ((lane >> 3) & 1) * 8;
    int ch  = 2*ks + (lane >> 4);
    return base + row*256 + (((ch ^ (row & 7))) << 4);
}
__device__ __forceinline__ uint32_t bfrag_addr(uint32_t base, int rbase, int ks, int lane){
    int row = rbase + (lane & 7) + ((lane >> 4) & 1) * 8;
    int ch  = 2*ks + ((lane >> 3) & 1);
    return base + row*256 + (((ch ^ (row & 7))) << 4);
}

// stage 128x128 bf16 tile (row-major src, 256B rows) into swizzled smem via cp.async
__device__ __forceinline__ void stage_cp(uint32_t dst, const __nv_bfloat16* __restrict__ src,
                                         int tid){
    const int kk = tid >> 1;                 // row 0..127
    const int c0 = (tid & 1) * 8;            // first chunk
    const char* s = (const char*)src + (size_t)kk*256 + (size_t)c0*16;
    const uint32_t drow = dst + kk*256;
    const int sw = kk & 7;
    #pragma unroll
    for(int i=0; i<8; ++i){
        int ch = c0 + i;
        cp16(drow + (((ch ^ sw)) << 4), s + i*16);
    }
}

// smem map for ksimtopk
#define OF_BBUF 65536
#define BBUF_SZ 69632
#define SM_SIM2 (OF_BBUF + 2*BBUF_SZ)   // 204800

// top-9 register insert
#define INS(vv, mm) do{ float _v = (vv); if(_v > minv){ int _m = (mm); \
    _Pragma("unroll") for(int u=0;u<TK;++u) if(u==minp){ tvv[u]=_v; tii[u]=_m; } \
    minv = tvv[0]; minp = 0; \
    _Pragma("unroll") for(int u=1;u<TK;++u) if(tvv[u]<minv){ minv=tvv[u]; minp=u; } } }while(0)

// ---------------- K1: L2-normalize; write fp32 [B,N,C] + bf16 hi/lo ------------
__global__ void knorm(const float* __restrict__ x){
    __shared__ float s[CC][33];
    __shared__ float rn[32];
    const int b  = blockIdx.y;
    const int n0 = blockIdx.x * 32;   // grid.x = 64 -> covers NPAD rows
    const int tid = threadIdx.x;      // 256

    #pragma unroll
    for(int it=0; it<16; ++it){
        int idx = it*256 + tid;
        int c = idx >> 5, nl = idx & 31;
        int n = n0 + nl;
        s[c][nl] = (n < NN) ? x[((size_t)b*CC + c)*NN + n] : 0.f;
    }
    __syncthreads();
    {
        int t = tid & 7, nl = tid >> 3;
        float ss = 0.f;
        #pragma unroll
        for(int c=t; c<CC; c+=8){ float v = s[c][nl]; ss += v*v; }
        ss += __shfl_down_sync(0xffffffffu, ss, 4);
        ss += __shfl_down_sync(0xffffffffu, ss, 2);
        ss += __shfl_down_sync(0xffffffffu, ss, 1);
        if(t == 0){
            float nrm = sqrtf(ss);
            rn[nl] = 1.f / fmaxf(nrm, 1e-12f);
        }
    }
    __syncthreads();
    #pragma unroll
    for(int it=0; it<16; ++it){
        int idx = it*256 + tid;
        int nl = idx >> 7, c = idx & 127;
        int n = n0 + nl;
        float f = s[c][nl] * rn[nl];               // exact 0 for padded rows
        if(n < NN) g_xn[((size_t)b*NN + n)*CC + c] = f;
        __nv_bfloat16 hi = __float2bfloat16(f);
        __nv_bfloat16 lo = __float2bfloat16(f - __bfloat162float(hi));
        size_t e = ((size_t)b*NPAD + n)*CC + c;
        g_xhi[e] = hi;
        g_xlo[e] = lo;
    }
}

// ---------------- K2: HMMA sim GEMM (bf16 3-split) + top-9 ---------------------
// 256 thr; CTA = 128 queries; warp grid 4(m) x 2(n): warp = 32q x 64k.
__global__ void __launch_bounds__(256,1) ksimtopk(){
    extern __shared__ char smc[];
    const uint32_t sb = smem_u32(smc);
    const int tid = threadIdx.x, lane = tid & 31, wid = tid >> 5;
    const int wm = wid >> 1, wn = wid & 1;
    const int b = blockIdx.y, q0 = blockIdx.x * 128;
    const __nv_bfloat16* Hb = g_xhi + (size_t)b*NPAD*CC;
    const __nv_bfloat16* Lb = g_xlo + (size_t)b*NPAD*CC;

    const uint32_t A_HI = sb;
    const uint32_t A_LO = sb + 32768;

    // stage A (hi+lo) and B tile 0 (hi+lo)
    stage_cp(A_HI, Hb + (size_t)q0*CC, tid);
    stage_cp(A_LO, Lb + (size_t)q0*CC, tid);
    stage_cp(sb + OF_BBUF,         Hb, tid);
    stage_cp(sb + OF_BBUF + 32768, Lb, tid);
    CP_COMMIT();

    float tvv[TK]; int tii[TK];
    #pragma unroll
    for(int u=0; u<TK; ++u){ tvv[u] = -1e30f; tii[u] = 0; }
    float minv = -1e30f; int minp = 0;

    const int r   = tid & 127;     // merge row
    const int half = tid >> 7;     // 0: keys 0-63, 1: keys 64-127

    for(int t=0; t<16; ++t){
        CP_WAIT0();
        __syncthreads();
        const uint32_t BH = sb + OF_BBUF + (uint32_t)(t&1)*BBUF_SZ;
        const uint32_t BL = BH + 32768;
        // prefetch next key tile into the other buffer
        if(t < 15){
            const uint32_t BN = sb + OF_BBUF + (uint32_t)((t+1)&1)*BBUF_SZ;
            stage_cp(BN,         Hb + (size_t)(t+1)*128*CC, tid);
            stage_cp(BN + 32768, Lb + (size_t)(t+1)*128*CC, tid);
            CP_COMMIT();
        }

        // ---- compute: warp does 32q x 64k, K=128, 3 split terms ----
        float acc[2][8][4];
        #pragma unroll
        for(int mt=0; mt<2; ++mt)
            #pragma unroll
            for(int nt=0; nt<8; ++nt)
                #pragma unroll
                for(int e=0; e<4; ++e) acc[mt][nt][e] = 0.f;

        #pragma unroll
        for(int ks=0; ks<8; ++ks){
            uint32_t aH0[4], aH1[4], aL0[4], aL1[4];
            ldsm4(afrag_addr(A_HI, 32*wm,      ks, lane), aH0);
            ldsm4(afrag_addr(A_HI, 32*wm + 16, ks, lane), aH1);
            ldsm4(afrag_addr(A_LO, 32*wm,      ks, lane), aL0);
            ldsm4(afrag_addr(A_LO, 32*wm + 16, ks, lane), aL1);
            #pragma unroll
            for(int np=0; np<4; ++np){
                uint32_t bH[4], bL[4];
                ldsm4(bfrag_addr(BH, 64*wn + 16*np, ks, lane), bH);
                ldsm4(bfrag_addr(BL, 64*wn + 16*np, ks, lane), bL);
                mma16816(acc[0][2*np],   aH0, bH[0], bH[1]);
                mma16816(acc[0][2*np+1], aH0, bH[2], bH[3]);
                mma16816(acc[1][2*np],   aH1, bH[0], bH[1]);
                mma16816(acc[1][2*np+1], aH1, bH[2], bH[3]);
                mma16816(acc[0][2*np],   aH0, bL[0], bL[1]);
                mma16816(acc[0][2*np+1], aH0, bL[2], bL[3]);
                mma16816(acc[1][2*np],   aH1, bL[0], bL[1]);
                mma16816(acc[1][2*np+1], aH1, bL[2], bL[3]);
                mma16816(acc[0][2*np],   aL0, bH[0], bH[1]);
                mma16816(acc[0][2*np+1], aL0, bH[2], bH[3]);
                mma16816(acc[1][2*np],   aL1, bH[0], bH[1]);
                mma16816(acc[1][2*np+1], aL1, bH[2], bH[3]);
            }
        }
        __syncthreads();   // all warps done reading B(cur)

        // ---- spill sim tile over the retired B buffer (128 x 132 fp32) ----
        float* Cb = (float*)(smc + OF_BBUF + (size_t)(t&1)*BBUF_SZ);
        {
            const int rr0 = 32*wm + (lane >> 2);
            const int cc0 = 64*wn + 2*(lane & 3);
            #pragma unroll
            for(int mt=0; mt<2; ++mt){
                #pragma unroll
                for(int nt=0; nt<8; ++nt){
                    int rr = rr0 + 16*mt, cc = cc0 + 8*nt;
                    *(float2*)&Cb[(size_t)rr*132 + cc] =
                        make_float2(acc[mt][nt][0], acc[mt][nt][1]);
                    *(float2*)&Cb[(size_t)(rr+8)*132 + cc] =
                        make_float2(acc[mt][nt][2], acc[mt][nt][3]);
                }
            }
        }
        __syncthreads();

        // ---- merge: 2 threads per query row, 64 keys each ----
        {
            const float* Crow = Cb + (size_t)r*132 + half*64;
            const int mbase = t*128 + half*64;
            const int cnt = min(64, NN - mbase);
            if(cnt == 64){
                #pragma unroll
                for(int jj=0; jj<16; ++jj){
                    float4 v4 = *(const float4*)&Crow[jj*4];
                    INS(v4.x, mbase + jj*4 + 0);
                    INS(v4.y, mbase + jj*4 + 1);
                    INS(v4.z, mbase + jj*4 + 2);
                    INS(v4.w, mbase + jj*4 + 3);
                }
            } else {
                for(int j=0; j<cnt; ++j) INS(Crow[j], mbase + j);
            }
        }
        __syncthreads();
    }

    // ---- combine the two half-lists (reuse A region) ----
    float* fv = (float*)smc;                 // [9][128]
    int*   fi = (int*)(smc + TK*128*4);      // [9][128]
    if(half == 1){
        #pragma unroll
        for(int u=0; u<TK; ++u){ fv[u*128 + r] = tvv[u]; fi[u*128 + r] = tii[u]; }
    }
    __syncthreads();
    if(half == 0){
        #pragma unroll
        for(int u=0; u<TK; ++u) INS(fv[u*128 + r], fi[u*128 + r]);
        const int q = q0 + r;
        if(q < NN){
            float s = 0.f;
            #pragma unroll
            for(int u=0; u<TK; ++u) s += tvv[u];
            float inv = 1.f / (s + 1e-6f);
            size_t base = ((size_t)b*NN + q)*TK;
            #pragma unroll
            for(int u=0; u<TK; ++u){
                g_vw[base + u] = tvv[u] * inv;
                g_ix[base + u] = tii[u];
            }
        }
    }
}

// ---------------- K3: out[r][:] = A[r][:] @ W  (rows x 128 @ 128 x 128) --------
__global__ void __launch_bounds__(256,2) kgemm(const float* __restrict__ A,
                                              const float* __restrict__ W,
                                              float* __restrict__ out, int rows){
    extern __shared__ float sm[];
    float* As = sm;            // [128][68]  A^T
    float* Ws = As + 128*68;   // [128][128] W row-major
    const int tid = threadIdx.x, lane = tid & 31, wq = tid >> 5;
    const int r0 = blockIdx.x * 64;

    #pragma unroll
    for(int it=0; it<32; ++it){
        int idx = it*256 + tid;
        int rl = idx >> 7, c = idx & 127;
        int rr = r0 + rl;
        As[c*68 + rl] = (rr < rows) ? A[(size_t)rr*CC + c] : 0.f;
    }
    #pragma unroll
    for(int it=0; it<64; ++it){ int idx = it*256 + tid; Ws[idx] = W[idx]; }
    __syncthreads();

    unsigned long long acc[4][4];
    #pragma unroll
    for(int k=0;k<4;++k)
        #pragma unroll
        for(int p=0;p<4;++p) acc[k][p] = 0ull;

    #pragma unroll 4
    for(int c=0; c<CC; ++c){
        ulonglong2 aA = *(const ulonglong2*)&As[c*68 + 8*wq];
        ulonglong2 aB = *(const ulonglong2*)&As[c*68 + 8*wq + 4];
        float4 bf = *(const float4*)&Ws[c*CC + 4*lane];
        unsigned long long bd0 = pk2(bf.x, bf.x);
        unsigned long long bd1 = pk2(bf.y, bf.y);
        unsigned long long bd2 = pk2(bf.z, bf.z);
        unsigned long long bd3 = pk2(bf.w, bf.w);
        acc[0][0]=f2fma(aA.x,bd0,acc[0][0]); acc[0][1]=f2fma(aA.y,bd0,acc[0][1]);
        acc[0][2]=f2fma(aB.x,bd0,acc[0][2]); acc[0][3]=f2fma(aB.y,bd0,acc[0][3]);
        acc[1][0]=f2fma(aA.x,bd1,acc[1][0]); acc[1][1]=f2fma(aA.y,bd1,acc[1][1]);
        acc[1][2]=f2fma(aB.x,bd1,acc[1][2]); acc[1][3]=f2fma(aB.y,bd1,acc[1][3]);
        acc[2][0]=f2fma(aA.x,bd2,acc[2][0]); acc[2][1]=f2fma(aA.y,bd2,acc[2][1]);
        acc[2][2]=f2fma(aB.x,bd2,acc[2][2]); acc[2][3]=f2fma(aB.y,bd2,acc[2][3]);
        acc[3][0]=f2fma(aA.x,bd3,acc[3][0]); acc[3][1]=f2fma(aA.y,bd3,acc[3][1]);
        acc[3][2]=f2fma(aB.x,bd3,acc[3][2]); acc[3][3]=f2fma(aB.y,bd3,acc[3][3]);
    }

    #pragma unroll
    for(int p=0; p<4; ++p){
        int rr = r0 + 8*wq + 2*p;
        float4 v0 = make_float4(lo2(acc[0][p]), lo2(acc[1][p]),
                                lo2(acc[2][p]), lo2(acc[3][p]));
        float4 v1 = make_float4(hi2(acc[0][p]), hi2(acc[1][p]),
                                hi2(acc[2][p]), hi2(acc[3][p]));
        if(rr     < rows) *(float4*)&out[(size_t)rr*CC + 4*lane]     = v0;
        if(rr + 1 < rows) *(float4*)&out[(size_t)(rr+1)*CC + 4*lane] = v1;
    }
}

// ---------------- K4: KNN gather + weighted sum + bias -------------------------
__global__ void kgather(const float* __restrict__ xt, const float* __restrict__ bias,
                        float* __restrict__ h){
    const int bn = blockIdx.x;            // 0..64799
    const int b  = bn / NN;
    __shared__ float vs[TK];
    __shared__ int   is[TK];
    const int tid = threadIdx.x;          // 128
    if(tid < TK){
        vs[tid] = g_vw[(size_t)bn*TK + tid];
        is[tid] = g_ix[(size_t)bn*TK + tid];
    }
    __syncthreads();
    const float* xb = xt + (size_t)b*NN*CC;
    float a = bias[tid];
    #pragma unroll
    for(int k=0; k<TK; ++k) a += vs[k] * xb[(size_t)is[k]*CC + tid];
    h[(size_t)bn*CC + tid] = a;
}

// ---------------- K5: GroupNorm stats (mean, rstd) per (b, group) --------------
__global__ void kgnstat(const float* __restrict__ h){
    const int bg = blockIdx.x;            // 0..127
    const int b = bg >> 2, g = bg & 3;
    const int tid = threadIdx.x;          // 256
    const float* hb = h + (size_t)b*NN*CC + g*CPG;
    float s = 0.f, s2 = 0.f;
    for(int i = tid; i < NN*CPG; i += 256){
        int n = i >> 5, cc = i & 31;
        float v = hb[(size_t)n*CC + cc];
        s += v; s2 += v*v;
    }
    __shared__ float rs[8], rs2[8];
    #pragma unroll
    for(int o=16; o; o>>=1){
        s  += __shfl_down_sync(0xffffffffu, s,  o);
        s2 += __shfl_down_sync(0xffffffffu, s2, o);
    }
    if((tid & 31) == 0){ rs[tid>>5] = s; rs2[tid>>5] = s2; }
    __syncthreads();
    if(tid < 8){
        s = rs[tid]; s2 = rs2[tid];
        #pragma unroll
        for(int o=4; o; o>>=1){
            s  += __shfl_down_sync(0xffu, s,  o);
            s2 += __shfl_down_sync(0xffu, s2, o);
        }
        if(tid == 0){
            const float cnt = (float)(NN*CPG);
            float mean = s / cnt;
            float var  = s2 / cnt - mean*mean;
            g_st[bg*2]     = mean;
            g_st[bg*2 + 1] = rsqrtf(var + 1e-5f);
        }
    }
}

// ---------------- K6: GN apply + SiLU (optional transpose to [B,C,N]) ----------
__global__ void kgnapply(const float* __restrict__ h, const float* __restrict__ gamma,
                         const float* __restrict__ beta, float* __restrict__ out,
                         int transpose){
    const size_t e = (size_t)blockIdx.x*256 + threadIdx.x;
    if(e >= (size_t)BB*NN*CC) return;
    const int c  = (int)(e & 127);
    const int bn = (int)(e >> 7);
    const int b = bn / NN, n = bn % NN;
    const int g = c >> 5;
    const float mean = g_st[(b*NG + g)*2];
    const float rstd = g_st[(b*NG + g)*2 + 1];
    float y = (h[e] - mean) * rstd * gamma[c] + beta[c];
    float sv = y / (1.f + expf(-y));
    if(transpose) out[((size_t)b*CC + c)*NN + n] = sv;
    else          out[e] = sv;
}

// ---------------- launch ----------------
extern "C" void kernel_launch(void* const* d_in, const int* in_sizes, int n_in,
                              void* d_out, int out_size){
    const float* x   = (const float*)d_in[0];
    const float* w1  = (const float*)d_in[1];
    const float* b1  = (const float*)d_in[2];
    const float* w2  = (const float*)d_in[3];
    const float* b2  = (const float*)d_in[4];
    const float* gm1 = (const float*)d_in[5];
    const float* bt1 = (const float*)d_in[6];
    const float* gm2 = (const float*)d_in[7];
    const float* bt2 = (const float*)d_in[8];
    float* out = (float*)d_out;

    const int SM_GEMM = (128*68 + 128*128)*4;                     // 100352
    cudaFuncSetAttribute(ksimtopk, cudaFuncAttributeMaxDynamicSharedMemorySize, SM_SIM2);
    cudaFuncSetAttribute(kgemm,    cudaFuncAttributeMaxDynamicSharedMemorySize, SM_GEMM);

    float *xn, *xt, *h;
    cudaGetSymbolAddress((void**)&xn, g_xn);
    cudaGetSymbolAddress((void**)&xt, g_xt);
    cudaGetSymbolAddress((void**)&h,  g_h);

    const int gemm_blocks = (ROWS_TOT + 63) / 64;   // 1013

    knorm<<<dim3(64, BB), 256>>>(x);
    ksimtopk<<<dim3(16, BB), 256, SM_SIM2>>>();

    // layer 1
    kgemm<<<gemm_blocks, 256, SM_GEMM>>>(xn, w1, xt, ROWS_TOT);
    kgather<<<ROWS_TOT, 128>>>(xt, b1, h);
    kgnstat<<<BB*NG, 256>>>(h);
    kgnapply<<<32400, 256>>>(h, gm1, bt1, xt, 0);    // of -> g_xt

    // layer 2 (g_xn is free now; reuse for xt2)
    kgemm<<<gemm_blocks, 256, SM_GEMM>>>(xt, w2, xn, ROWS_TOT);
    kgather<<<ROWS_TOT, 128>>>(xn, b2, h);
    kgnstat<<<BB*NG, 256>>>(h);
    kgnapply<<<32400, 256>>>(h, gm2, bt2, out, 1);   // final, [B,C,H,W]
}